// round 1
// baseline (speedup 1.0000x reference)
#include <cuda_runtime.h>
#include <math.h>

// iNGPDW: fused hash-grid encode + erf scaling + 40->64->64->13 SELU MLP.
// One thread per point. Weights transposed into shared memory (broadcast
// vectorized LDS.128 reads), activations fully register-resident.

constexpr int NLEV = 10;        // hash-grid levels
constexpr int TBL  = 1 << 16;   // table entries per level
constexpr int IND  = 40;        // NLEV * 4 features
constexpr int HIDN = 64;
constexpr int OUTD = 13;

struct ResParams { int res[NLEV]; };

__device__ __forceinline__ float selu_f(float v) {
    const float sc = 1.0507009873554805f;
    const float al = 1.6732632423543772f;
    return v > 0.0f ? sc * v : sc * (al * expm1f(v));
}

__global__ __launch_bounds__(256)
void ngp_fused_kernel(const float*  __restrict__ gx,     // [N,3]
                      const float*  __restrict__ gcr,    // [N]
                      const float4* __restrict__ gtab,   // [NLEV*TBL] float4
                      const float*  __restrict__ gW1,    // [40,64]
                      const float*  __restrict__ gb1,    // [64]
                      const float*  __restrict__ gW2,    // [64,64]
                      const float*  __restrict__ gb2,    // [64]
                      const float*  __restrict__ gW3,    // [64,13]
                      const float*  __restrict__ gb3,    // [13]
                      float*        __restrict__ gout,   // [N,13]
                      int N, ResParams rp)
{
    __shared__ float sW1[HIDN * IND];    // transposed: sW1[j*40 + k] = W1[k,j]
    __shared__ float sW2[HIDN * HIDN];   // transposed: sW2[j*64 + k] = W2[k,j]
    __shared__ float sW3[OUTD * HIDN];   // transposed: sW3[j*64 + k] = W3[k,j]
    __shared__ float sB1[HIDN];
    __shared__ float sB2[HIDN];
    __shared__ float sB3[16];

    const int tid = threadIdx.x;
    for (int i = tid; i < HIDN * IND; i += blockDim.x) {
        int j = i / IND, k = i - j * IND;
        sW1[i] = gW1[k * HIDN + j];
    }
    for (int i = tid; i < HIDN * HIDN; i += blockDim.x) {
        int j = i >> 6, k = i & 63;
        sW2[i] = gW2[k * HIDN + j];
    }
    for (int i = tid; i < OUTD * HIDN; i += blockDim.x) {
        int j = i >> 6, k = i & 63;
        sW3[i] = gW3[k * OUTD + j];
    }
    if (tid < HIDN) { sB1[tid] = gb1[tid]; sB2[tid] = gb2[tid]; }
    if (tid < OUTD) { sB3[tid] = gb3[tid]; }
    __syncthreads();

    const int n = blockIdx.x * blockDim.x + tid;
    if (n >= N) return;

    const float x0 = gx[3 * n + 0];
    const float x1 = gx[3 * n + 1];
    const float x2 = gx[3 * n + 2];
    const float crs = gcr[n] * 0.5f;    // SCALE_MULTI

    float h[IND];

    // ---- hash-grid encoding + erf scaling ----
    #pragma unroll
    for (int l = 0; l < NLEV; l++) {
        const float rf = (float)rp.res[l];
        const float xs0 = x0 * rf, xs1 = x1 * rf, xs2 = x2 * rf;
        const float fb0 = floorf(xs0), fb1 = floorf(xs1), fb2 = floorf(xs2);
        const float f0 = xs0 - fb0, f1 = xs1 - fb1, f2 = xs2 - fb2;
        const float g0 = 1.0f - f0, g1 = 1.0f - f1, g2 = 1.0f - f2;
        const unsigned c0 = (unsigned)fb0, c1 = (unsigned)fb1, c2 = (unsigned)fb2;

        float a0 = 0.f, a1 = 0.f, a2 = 0.f, a3 = 0.f;
        #pragma unroll
        for (int c = 0; c < 8; c++) {
            const unsigned ox = (c >> 2) & 1u, oy = (c >> 1) & 1u, oz = c & 1u;
            unsigned hsh = (c0 + ox)
                         ^ ((c1 + oy) * 2654435761u)
                         ^ ((c2 + oz) * 805459861u);
            const unsigned idx = hsh & (unsigned)(TBL - 1);
            const float4 t = __ldg(&gtab[(unsigned)(l * TBL) + idx]);
            const float w = (ox ? f0 : g0) * (oy ? f1 : g1) * (oz ? f2 : g2);
            a0 = fmaf(w, t.x, a0);
            a1 = fmaf(w, t.y, a1);
            a2 = fmaf(w, t.z, a2);
            a3 = fmaf(w, t.w, a3);
        }
        // scaling = erf(1/sqrt(max(PLS*4*l*cr_s, 1e-12)))
        const float denom = fmaxf((8.0f * (float)l) * crs, 1e-12f);
        const float scal = erff(1.0f / sqrtf(denom));
        h[0 * NLEV + l] = a0 * scal;
        h[1 * NLEV + l] = a1 * scal;
        h[2 * NLEV + l] = a2 * scal;
        h[3 * NLEV + l] = a3 * scal;
    }

    // ---- layer 1: 40 -> 64, SELU ----
    float a[HIDN];
    #pragma unroll 4
    for (int j = 0; j < HIDN; j++) {
        float acc = sB1[j];
        const float4* w4 = reinterpret_cast<const float4*>(&sW1[j * IND]);
        #pragma unroll
        for (int k4 = 0; k4 < IND / 4; k4++) {
            const float4 w = w4[k4];
            acc = fmaf(h[4 * k4 + 0], w.x, acc);
            acc = fmaf(h[4 * k4 + 1], w.y, acc);
            acc = fmaf(h[4 * k4 + 2], w.z, acc);
            acc = fmaf(h[4 * k4 + 3], w.w, acc);
        }
        a[j] = selu_f(acc);
    }

    // ---- layer 2: 64 -> 64, SELU ----
    float bact[HIDN];
    #pragma unroll 4
    for (int j = 0; j < HIDN; j++) {
        float acc = sB2[j];
        const float4* w4 = reinterpret_cast<const float4*>(&sW2[j * HIDN]);
        #pragma unroll
        for (int k4 = 0; k4 < HIDN / 4; k4++) {
            const float4 w = w4[k4];
            acc = fmaf(a[4 * k4 + 0], w.x, acc);
            acc = fmaf(a[4 * k4 + 1], w.y, acc);
            acc = fmaf(a[4 * k4 + 2], w.z, acc);
            acc = fmaf(a[4 * k4 + 3], w.w, acc);
        }
        bact[j] = selu_f(acc);
    }

    // ---- layer 3: 64 -> 13, linear ----
    float* op = gout + (size_t)n * OUTD;
    #pragma unroll
    for (int j = 0; j < OUTD; j++) {
        float acc = sB3[j];
        const float4* w4 = reinterpret_cast<const float4*>(&sW3[j * HIDN]);
        #pragma unroll
        for (int k4 = 0; k4 < HIDN / 4; k4++) {
            const float4 w = w4[k4];
            acc = fmaf(bact[4 * k4 + 0], w.x, acc);
            acc = fmaf(bact[4 * k4 + 1], w.y, acc);
            acc = fmaf(bact[4 * k4 + 2], w.z, acc);
            acc = fmaf(bact[4 * k4 + 3], w.w, acc);
        }
        op[j] = acc;
    }
}

extern "C" void kernel_launch(void* const* d_in, const int* in_sizes, int n_in,
                              void* d_out, int out_size) {
    const float*  x   = (const float*)d_in[0];
    const float*  cr  = (const float*)d_in[1];
    const float4* tab = (const float4*)d_in[2];
    const float*  W1  = (const float*)d_in[3];
    const float*  b1  = (const float*)d_in[4];
    const float*  W2  = (const float*)d_in[5];
    const float*  b2  = (const float*)d_in[6];
    const float*  W3  = (const float*)d_in[7];
    const float*  b3  = (const float*)d_in[8];
    float* out = (float*)d_out;

    const int N = in_sizes[0] / 3;

    // Replicate the reference's resolution computation with identical libm
    // double-precision calls (floor(16*b^9) is within ~1e-11 of 16384, so the
    // rounding sequence must match exactly).
    ResParams rp;
    const double B = exp((log(16.0 * pow(2.0, 10.0)) - log(16.0)) / 9.0);
    for (int l = 0; l < NLEV; l++) {
        rp.res[l] = (int)floor(16.0 * pow(B, (double)l));
    }

    const int threads = 256;
    const int blocks = (N + threads - 1) / threads;
    ngp_fused_kernel<<<blocks, threads>>>(x, cr, tab, W1, b1, W2, b2, W3, b3,
                                          out, N, rp);
}